// round 15
// baseline (speedup 1.0000x reference)
#include <cuda_runtime.h>
#include <cuda_fp16.h>
#include <math.h>
#include <stdint.h>

#define NN 50000
#define RR 3
#define EE 600000
#define DD 128
#define LL 3
#define SCAN_B 49   // ceil(50000/1024)

// ---------------- scratch (device globals) ----------------
__device__ __half g_z[(size_t)RR * NN * DD];       // projected features, fp16
__device__ __half g_wt[(size_t)LL * RR * DD * DD]; // W fp16, transposed [n][k]
__device__ __half g_hn[(size_t)NN * DD];           // normalized h, fp16
__device__ float g_el[RR * NN];
__device__ float g_er[RR * NN];
__device__ float g_alpha[(size_t)RR * EE];         // per-edge softmax weight
__device__ int   g_cnt[RR * NN];
__device__ int   g_off[RR * (NN + 1)];
__device__ int   g_part[RR * 64];
__device__ int   g_csr_src[RR * EE];
__device__ float g_b0[(size_t)NN * DD];            // pre-norm layer output
__device__ float g_sum[DD];
__device__ float g_sumsq[DD];
__device__ float g_scale[DD];
__device__ float g_shift[DD];
__device__ int   g_bar;                            // last-block counter

// ---------------- CSR build (once per launch) ----------------
__global__ void count_kernel(const int* __restrict__ dst) {
    int r = blockIdx.y;
    int e = blockIdx.x * blockDim.x + threadIdx.x;
    if (e < EE) atomicAdd(&g_cnt[r * NN + dst[(size_t)r * EE + e]], 1);
}

__global__ void scan1_kernel() {
    int r = blockIdx.y;
    int b = blockIdx.x;
    int i = b * 1024 + threadIdx.x;
    __shared__ int s[1024];
    int v = (i < NN) ? g_cnt[r * NN + i] : 0;
    s[threadIdx.x] = v;
    __syncthreads();
    for (int o = 1; o < 1024; o <<= 1) {
        int t = (threadIdx.x >= o) ? s[threadIdx.x - o] : 0;
        __syncthreads();
        s[threadIdx.x] += t;
        __syncthreads();
    }
    if (i < NN) {
        g_off[r * (NN + 1) + i] = s[threadIdx.x] - v;
        g_cnt[r * NN + i] = 0;
    }
    if (threadIdx.x == 1023) g_part[r * 64 + b] = s[1023];
}

__global__ void scan2_kernel() {   // warp-scan of 49 partials per etype
    int w = threadIdx.x >> 5;
    int l = threadIdx.x & 31;
    if (w >= RR) return;
    int i0 = 2 * l, i1 = 2 * l + 1;
    int v0 = (i0 < SCAN_B) ? g_part[w * 64 + i0] : 0;
    int v1 = (i1 < SCAN_B) ? g_part[w * 64 + i1] : 0;
    int s = v0 + v1;
    int incl = s;
#pragma unroll
    for (int o = 1; o < 32; o <<= 1) {
        int t = __shfl_up_sync(0xFFFFFFFFu, incl, o);
        if (l >= o) incl += t;
    }
    int base = incl - s;
    if (i0 < SCAN_B) g_part[w * 64 + i0] = base;
    if (i1 < SCAN_B) g_part[w * 64 + i1] = base + v0;
    int total = __shfl_sync(0xFFFFFFFFu, incl, 31);
    if (l == 0) g_off[w * (NN + 1) + NN] = total;
}

__global__ void scan3_kernel() {
    int r = blockIdx.y;
    int b = blockIdx.x;
    int i = b * 1024 + threadIdx.x;
    if (i < NN) g_off[r * (NN + 1) + i] += g_part[r * 64 + b];
}

__global__ void fill_kernel(const int* __restrict__ src, const int* __restrict__ dst) {
    int r = blockIdx.y;
    int e = blockIdx.x * blockDim.x + threadIdx.x;
    if (e >= EE) return;
    int d = dst[(size_t)r * EE + e];
    int pos = g_off[r * (NN + 1) + d] + atomicAdd(&g_cnt[r * NN + d], 1);
    g_csr_src[(size_t)r * EE + pos] = src[(size_t)r * EE + e];
}

// ---------------- one-time W -> fp16 transposed (+ zero g_cnt) ----------------
__global__ void wconv_kernel(const float* __restrict__ Ws) {
    int mat = blockIdx.x;
    const float* W = Ws + (size_t)mat * DD * DD;
    __half* wt = g_wt + (size_t)mat * DD * DD;
    for (int idx = threadIdx.x; idx < DD * DD; idx += blockDim.x) {
        int k = idx >> 7, n = idx & 127;
        wt[n * DD + k] = __float2half(W[idx]);
    }
    int gt = blockIdx.x * blockDim.x + threadIdx.x;
    for (int i = gt; i < RR * NN; i += gridDim.x * blockDim.x) g_cnt[i] = 0;
}

// ---------------- x -> fp16 (layer 0 input) ----------------
__global__ void xconv_kernel(const float* __restrict__ x, __half* __restrict__ hn) {
    size_t i = (size_t)blockIdx.x * blockDim.x + threadIdx.x;
    if (i >= (size_t)NN * DD / 4) return;
    float4 v = ((const float4*)x)[i];
    __half2 h0 = __float22half2_rn(make_float2(v.x, v.y));
    __half2 h1 = __float22half2_rn(make_float2(v.z, v.w));
    uint2 w;
    w.x = *(uint32_t*)&h0; w.y = *(uint32_t*)&h1;
    ((uint2*)hn)[i] = w;
}

// ---------------- BN-apply -> fp16 (inter-layer) ----------------
__global__ void hnconv_kernel(const float* __restrict__ t, __half* __restrict__ hn) {
    size_t i = (size_t)blockIdx.x * blockDim.x + threadIdx.x;
    if (i >= (size_t)NN * DD / 4) return;
    int c4 = (int)(i & 31) * 4;
    float4 v = ((const float4*)t)[i];
    v.x = v.x * g_scale[c4 + 0] + g_shift[c4 + 0];
    v.y = v.y * g_scale[c4 + 1] + g_shift[c4 + 1];
    v.z = v.z * g_scale[c4 + 2] + g_shift[c4 + 2];
    v.w = v.w * g_scale[c4 + 3] + g_shift[c4 + 3];
    __half2 h0 = __float22half2_rn(make_float2(v.x, v.y));
    __half2 h1 = __float22half2_rn(make_float2(v.z, v.w));
    uint2 w;
    w.x = *(uint32_t*)&h0; w.y = *(uint32_t*)&h1;
    ((uint2*)hn)[i] = w;
}

__global__ void bnnorm_kernel(const float* __restrict__ t, float* __restrict__ outp) {
    size_t i = (size_t)blockIdx.x * blockDim.x + threadIdx.x;
    if (i >= (size_t)NN * DD / 4) return;
    int c4 = (int)(i & 31) * 4;
    float4 v = ((const float4*)t)[i];
    v.x = v.x * g_scale[c4 + 0] + g_shift[c4 + 0];
    v.y = v.y * g_scale[c4 + 1] + g_shift[c4 + 1];
    v.z = v.z * g_scale[c4 + 2] + g_shift[c4 + 2];
    v.w = v.w * g_scale[c4 + 3] + g_shift[c4 + 3];
    ((float4*)outp)[i] = v;
}

// ---------------- fp16 HMMA GEMM z = hn @ W  + el/er epilogue ----------------
#define PAD 136   // smem pitch in halves (conflict-free)

#define MMA_F16(c, a, b0, b1)                                                 \
    asm volatile(                                                             \
        "mma.sync.aligned.m16n8k16.row.col.f32.f16.f16.f32 "                  \
        "{%0,%1,%2,%3},{%4,%5,%6,%7},{%8,%9},{%0,%1,%2,%3};"                  \
        : "+f"((c)[0]), "+f"((c)[1]), "+f"((c)[2]), "+f"((c)[3])              \
        : "r"((a)[0]), "r"((a)[1]), "r"((a)[2]), "r"((a)[3]),                 \
          "r"(b0), "r"(b1))

#define LDMX4(r0, r1, r2, r3, addr)                                           \
    asm volatile(                                                             \
        "ldmatrix.sync.aligned.m8n8.x4.shared.b16 {%0,%1,%2,%3}, [%4];"       \
        : "=r"(r0), "=r"(r1), "=r"(r2), "=r"(r3) : "r"(addr))

__global__ __launch_bounds__(256) void gemm_hmma_kernel(
    const __half* __restrict__ hn,       // [NN, DD] fp16 normalized
    const __half* __restrict__ wt_layer, // [RR, DD(n), DD(k)] fp16 transposed
    const float* __restrict__ al_layer,
    const float* __restrict__ ar_layer)
{
    extern __shared__ __half sm[];
    __half* As = sm;               // [128][PAD]
    __half* Bs = sm + 128 * PAD;   // [128][PAD]
    __shared__ float s_al[DD], s_ar[DD];
    __shared__ float s_el[128][2], s_er[128][2];

    int r = blockIdx.y;
    int rowBase = blockIdx.x * 128;
    int tid  = threadIdx.x;
    int lane = tid & 31;
    int wid  = tid >> 5;
    int mw   = wid >> 1;   // 0..3
    int nw   = wid & 1;    // 0..1
    int l8 = lane & 7;
    int lj = lane >> 3;

    if (tid < DD) {
        s_al[tid] = al_layer[(size_t)r * DD + tid];
        s_ar[tid] = ar_layer[(size_t)r * DD + tid];
    }

    // ---- stage A: fp16 uint4 copies (clamped rows; stores guarded later) ----
    {
        const uint4* hp = (const uint4*)hn;
        for (int u = tid; u < 128 * 16; u += 256) {
            int row = u >> 4;
            int k8  = (u & 15) * 8;
            int grow = rowBase + row;
            if (grow > NN - 1) grow = NN - 1;
            *(uint4*)(As + row * PAD + k8) = hp[(size_t)grow * 16 + (u & 15)];
        }
    }
    // ---- stage B ----
    {
        const uint4* wt = (const uint4*)(wt_layer + (size_t)r * DD * DD);
        for (int u = tid; u < 128 * 16; u += 256) {
            int n  = u >> 4;
            int k8 = (u & 15) * 8;
            *(uint4*)(Bs + n * PAD + k8) = wt[u];
        }
    }
    __syncthreads();

    float acc[2][8][4];
#pragma unroll
    for (int mt = 0; mt < 2; mt++)
#pragma unroll
        for (int nt = 0; nt < 8; nt++)
#pragma unroll
            for (int c = 0; c < 4; c++) acc[mt][nt][c] = 0.f;

#pragma unroll
    for (int k16 = 0; k16 < 8; k16++) {
        int kk = k16 * 16;
        uint32_t a[2][4];
#pragma unroll
        for (int mt = 0; mt < 2; mt++) {
            const __half* pa = As + (mw * 32 + mt * 16 + l8 + 8 * (lj & 1)) * PAD
                                  + kk + 8 * (lj >> 1);
            LDMX4(a[mt][0], a[mt][1], a[mt][2], a[mt][3],
                  (uint32_t)__cvta_generic_to_shared(pa));
        }
#pragma unroll
        for (int np = 0; np < 4; np++) {   // each covers nt = 2np, 2np+1
            const __half* pb = Bs + (nw * 64 + np * 16 + l8 + 8 * (lj >> 1)) * PAD
                                  + kk + 8 * (lj & 1);
            uint32_t b0, b1, b2, b3;
            LDMX4(b0, b1, b2, b3, (uint32_t)__cvta_generic_to_shared(pb));
#pragma unroll
            for (int mt = 0; mt < 2; mt++) {
                MMA_F16(acc[mt][2 * np],     a[mt], b0, b1);
                MMA_F16(acc[mt][2 * np + 1], a[mt], b2, b3);
            }
        }
    }

    // ---- epilogue: z store (fp16) + attention dots (fp32) ----
    __half* zr = g_z + (size_t)r * NN * DD;
    float pl[2][2] = {{0.f, 0.f}, {0.f, 0.f}};
    float pr[2][2] = {{0.f, 0.f}, {0.f, 0.f}};
#pragma unroll
    for (int mt = 0; mt < 2; mt++) {
        int row0 = rowBase + mw * 32 + mt * 16 + (lane >> 2);
        int row1 = row0 + 8;
#pragma unroll
        for (int nt = 0; nt < 8; nt++) {
            int nc = nw * 64 + nt * 8 + 2 * (lane & 3);
            float al0 = s_al[nc], al1 = s_al[nc + 1];
            float ar0 = s_ar[nc], ar1 = s_ar[nc + 1];
            pl[mt][0] += acc[mt][nt][0] * al0 + acc[mt][nt][1] * al1;
            pr[mt][0] += acc[mt][nt][0] * ar0 + acc[mt][nt][1] * ar1;
            pl[mt][1] += acc[mt][nt][2] * al0 + acc[mt][nt][3] * al1;
            pr[mt][1] += acc[mt][nt][2] * ar0 + acc[mt][nt][3] * ar1;
            if (row0 < NN)
                *(__half2*)(zr + (size_t)row0 * DD + nc) =
                    __float22half2_rn(make_float2(acc[mt][nt][0], acc[mt][nt][1]));
            if (row1 < NN)
                *(__half2*)(zr + (size_t)row1 * DD + nc) =
                    __float22half2_rn(make_float2(acc[mt][nt][2], acc[mt][nt][3]));
        }
    }
#pragma unroll
    for (int mt = 0; mt < 2; mt++)
#pragma unroll
        for (int i = 0; i < 2; i++) {
#pragma unroll
            for (int o = 1; o <= 2; o <<= 1) {
                pl[mt][i] += __shfl_xor_sync(0xFFFFFFFFu, pl[mt][i], o);
                pr[mt][i] += __shfl_xor_sync(0xFFFFFFFFu, pr[mt][i], o);
            }
            if ((lane & 3) == 0) {
                int rl = mw * 32 + mt * 16 + (lane >> 2) + 8 * i;
                s_el[rl][nw] = pl[mt][i];
                s_er[rl][nw] = pr[mt][i];
            }
        }
    __syncthreads();
    if (tid < 128) {
        int g = rowBase + tid;
        if (g < NN) {
            g_el[r * NN + g] = s_el[tid][0] + s_el[tid][1];
            g_er[r * NN + g] = s_er[tid][0] + s_er[tid][1];
        }
    }
}

// ---------------- per-layer edge softmax weights (two-pass, normalized alpha) ----
__global__ void edgew_kernel() {
    int r = blockIdx.y;
    int n = blockIdx.x * blockDim.x + threadIdx.x;
    if (n >= NN) return;
    int b0 = g_off[r * (NN + 1) + n];
    int b1 = g_off[r * (NN + 1) + n + 1];
    if (b0 >= b1) return;
    float ern = g_er[r * NN + n];
    const float* elr = g_el + r * NN;
    const int*   cs  = g_csr_src + (size_t)r * EE;
    float* ax = g_alpha + (size_t)r * EE;
    float ssum = 0.f;
    for (int idx = b0; idx < b1; ++idx) {   // pass 1: exp + store
        float v = elr[cs[idx]] + ern;
        v = v > 0.f ? v : 0.2f * v;
        float e = __expf(v);
        ax[idx] = e;
        ssum += e;
    }
    float inv = 1.f / ssum;
    for (int idx = b0; idx < b1; ++idx)     // pass 2: scale in place
        ax[idx] *= inv;
}

// ---------------- fused aggregation + BN stats + BN finalize ----------------
__global__ __launch_bounds__(256) void heavy_all_kernel(
    const __half* __restrict__ hn,        // [NN, DD] fp16 normalized input
    const float* __restrict__ bias_layer, // [RR, DD]
    float* __restrict__ t,
    int dorelu,
    const float* __restrict__ gamma,
    const float* __restrict__ beta)
{
    int lane = threadIdx.x & 31;
    int wid  = threadIdx.x >> 5;

    float4 bv[RR];
#pragma unroll
    for (int r = 0; r < RR; r++)
        bv[r] = *(const float4*)(bias_layer + r * DD + lane * 4);

    float4 bsum = make_float4(0.f, 0.f, 0.f, 0.f);
    float4 bsq  = make_float4(0.f, 0.f, 0.f, 0.f);

    for (int n = blockIdx.x * 8 + wid; n < NN; n += gridDim.x * 8) {
        uint2 hw = *(const uint2*)(hn + (size_t)n * DD + lane * 4);
        __half2 hq0 = *(__half2*)&hw.x;
        __half2 hq1 = *(__half2*)&hw.y;
        float2 hf0 = __half22float2(hq0);
        float2 hf1 = __half22float2(hq1);
        float4 hv = make_float4(hf0.x, hf0.y, hf1.x, hf1.y);

        float4 tot = make_float4(0.f, 0.f, 0.f, 0.f);
#pragma unroll
        for (int r = 0; r < RR; r++) {
            int b0 = g_off[r * (NN + 1) + n];
            int b1 = g_off[r * (NN + 1) + n + 1];
            const int*   cs = g_csr_src + (size_t)r * EE;
            const float* ax = g_alpha + (size_t)r * EE;
            const __half2* zp = (const __half2*)g_z + (size_t)r * NN * (DD / 2);

            // software-pipelined unroll x2: prefetch next pair's (s,a) before
            // issuing current pair's z loads, breaking the cs->z load chain.
            float4 acc0 = make_float4(0.f, 0.f, 0.f, 0.f);
            float4 acc1 = make_float4(0.f, 0.f, 0.f, 0.f);
            int cnt = b1 - b0;
            int idx = b0;
            int s0 = 0, s1 = 0;
            float a0 = 0.f, a1 = 0.f;
            if (cnt > 0) { s0 = cs[idx];     a0 = ax[idx]; }
            if (cnt > 1) { s1 = cs[idx + 1]; a1 = ax[idx + 1]; }
            while (cnt >= 2) {
                uint2 w0 = *(const uint2*)(zp + (size_t)s0 * (DD / 2) + lane * 2);
                uint2 w1 = *(const uint2*)(zp + (size_t)s1 * (DD / 2) + lane * 2);
                float ca0 = a0, ca1 = a1;
                idx += 2; cnt -= 2;
                if (cnt > 0) { s0 = cs[idx];     a0 = ax[idx]; }
                if (cnt > 1) { s1 = cs[idx + 1]; a1 = ax[idx + 1]; }
                float2 f00 = __half22float2(*(__half2*)&w0.x);
                float2 f01 = __half22float2(*(__half2*)&w0.y);
                float2 f10 = __half22float2(*(__half2*)&w1.x);
                float2 f11 = __half22float2(*(__half2*)&w1.y);
                acc0.x += ca0 * f00.x; acc0.y += ca0 * f00.y;
                acc0.z += ca0 * f01.x; acc0.w += ca0 * f01.y;
                acc1.x += ca1 * f10.x; acc1.y += ca1 * f10.y;
                acc1.z += ca1 * f11.x; acc1.w += ca1 * f11.y;
            }
            if (cnt == 1) {
                uint2 w0 = *(const uint2*)(zp + (size_t)s0 * (DD / 2) + lane * 2);
                float2 f00 = __half22float2(*(__half2*)&w0.x);
                float2 f01 = __half22float2(*(__half2*)&w0.y);
                acc0.x += a0 * f00.x; acc0.y += a0 * f00.y;
                acc0.z += a0 * f01.x; acc0.w += a0 * f01.y;
            }
            float4 v4 = make_float4(acc0.x + acc1.x + hv.x + bv[r].x,
                                    acc0.y + acc1.y + hv.y + bv[r].y,
                                    acc0.z + acc1.z + hv.z + bv[r].z,
                                    acc0.w + acc1.w + hv.w + bv[r].w);
            if (dorelu) {
                v4.x = fmaxf(v4.x, 0.f); v4.y = fmaxf(v4.y, 0.f);
                v4.z = fmaxf(v4.z, 0.f); v4.w = fmaxf(v4.w, 0.f);
            }
            tot.x += v4.x; tot.y += v4.y; tot.z += v4.z; tot.w += v4.w;
        }
        *(float4*)(t + (size_t)n * DD + lane * 4) = tot;
        bsum.x += tot.x; bsum.y += tot.y; bsum.z += tot.z; bsum.w += tot.w;
        bsq.x += tot.x * tot.x; bsq.y += tot.y * tot.y;
        bsq.z += tot.z * tot.z; bsq.w += tot.w * tot.w;
    }

    // block-level BN stat reduction
    __shared__ float sb[8][DD], sb2[8][DD];
    *(float4*)(&sb[wid][lane * 4])  = bsum;
    *(float4*)(&sb2[wid][lane * 4]) = bsq;
    __syncthreads();
    int tid = threadIdx.x;
    if (tid < DD) {
        float s = 0.f;
#pragma unroll
        for (int w = 0; w < 8; w++) s += sb[w][tid];
        atomicAdd(&g_sum[tid], s);
    } else {
        int col = tid - DD;
        float s2 = 0.f;
#pragma unroll
        for (int w = 0; w < 8; w++) s2 += sb2[w][col];
        atomicAdd(&g_sumsq[col], s2);
    }

    // last block finalizes BN affine (and resets for replay determinism)
    __shared__ int s_last;
    __threadfence();
    if (tid == 0) s_last = (atomicAdd(&g_bar, 1) == (int)gridDim.x - 1);
    __syncthreads();
    if (s_last) {
        if (tid < DD) {
            float invN = 1.f / (float)NN;
            float mu  = g_sum[tid] * invN;
            float var = g_sumsq[tid] * invN - mu * mu;
            float rs  = rsqrtf(var + 1e-5f);
            float g   = gamma[tid];
            g_scale[tid] = rs * g;
            g_shift[tid] = beta[tid] - mu * rs * g;
            g_sum[tid] = 0.f;
            g_sumsq[tid] = 0.f;
        }
        if (tid == 0) g_bar = 0;
    }
}

// ---------------- launcher ----------------
extern "C" void kernel_launch(void* const* d_in, const int* in_sizes, int n_in,
                              void* d_out, int out_size) {
    const float* x     = (const float*)d_in[0];
    const int*   src   = (const int*)d_in[1];
    const int*   dst   = (const int*)d_in[2];
    const float* Ws    = (const float*)d_in[3];
    const float* attnl = (const float*)d_in[4];
    const float* attnr = (const float*)d_in[5];
    const float* bias  = (const float*)d_in[6];
    const float* gamma = (const float*)d_in[7];
    const float* beta  = (const float*)d_in[8];
    float* out = (float*)d_out;

    float* p_b0 = nullptr;
    __half *p_wt = nullptr, *p_hn = nullptr;
    cudaGetSymbolAddress((void**)&p_b0, g_b0);
    cudaGetSymbolAddress((void**)&p_wt, g_wt);
    cudaGetSymbolAddress((void**)&p_hn, g_hn);

    const int SMEM_BYTES = 2 * 128 * PAD * (int)sizeof(__half);  // 69632
    cudaFuncSetAttribute(gemm_hmma_kernel,
                         cudaFuncAttributeMaxDynamicSharedMemorySize, SMEM_BYTES);

    dim3 gemm_grid((NN + 127) / 128, RR);
    dim3 edge_grid((EE + 255) / 256, RR);
    dim3 scan_grid(SCAN_B, RR);
    dim3 node_grid((NN + 255) / 256, RR);
    int heavy_blocks = 1184;
    int norm_blocks  = ((NN * DD / 4) + 255) / 256;

    // ---- setup ----
    wconv_kernel<<<LL * RR, 256>>>(Ws);                 // #1 (also zeroes g_cnt)
    xconv_kernel<<<norm_blocks, 256>>>(x, p_hn);        // #2
    count_kernel<<<edge_grid, 256>>>(dst);              // #3
    gemm_hmma_kernel<<<gemm_grid, 256, SMEM_BYTES>>>(   // #4: layer-0 GEMM
        p_hn, p_wt, attnl, attnr);
    scan1_kernel<<<scan_grid, 1024>>>();                // #5
    scan2_kernel<<<1, 96>>>();                          // #6
    scan3_kernel<<<scan_grid, 1024>>>();                // #7
    fill_kernel<<<edge_grid, 256>>>(src, dst);          // #8

    for (int i = 0; i < LL; i++) {
        float* tbuf = (i < LL - 1) ? p_b0 : out;

        if (i > 0) {
            gemm_hmma_kernel<<<gemm_grid, 256, SMEM_BYTES>>>(
                p_hn,
                p_wt  + (size_t)i * RR * DD * DD,
                attnl + (size_t)i * RR * DD,
                attnr + (size_t)i * RR * DD);
        }
        edgew_kernel<<<node_grid, 256>>>();
        heavy_all_kernel<<<heavy_blocks, 256>>>(
            p_hn,
            bias + (size_t)i * RR * DD,
            tbuf, /*dorelu=*/(i < LL - 1),
            gamma + (size_t)i * DD,
            beta  + (size_t)i * DD);
        if (i < LL - 1)
            hnconv_kernel<<<norm_blocks, 256>>>(tbuf, p_hn);
        else
            bnnorm_kernel<<<norm_blocks, 256>>>(out, out);
    }
}

// round 16
// speedup vs baseline: 1.1160x; 1.1160x over previous
#include <cuda_runtime.h>
#include <cuda_fp16.h>
#include <math.h>
#include <stdint.h>

#define NN 50000
#define RR 3
#define EE 600000
#define DD 128
#define LL 3
#define SCAN_B 49   // ceil(50000/1024)

// ---------------- scratch (device globals) ----------------
__device__ __half g_z[(size_t)RR * NN * DD];       // projected features, fp16
__device__ __half g_wt[(size_t)LL * RR * DD * DD]; // W fp16, transposed [n][k]
__device__ __half g_hn[(size_t)NN * DD];           // normalized h, fp16
__device__ float g_el[RR * NN];
__device__ float g_er[RR * NN];
__device__ float g_alpha[(size_t)RR * EE];         // per-edge softmax weight
__device__ int   g_cnt[RR * NN];
__device__ int   g_off[RR * (NN + 1)];
__device__ int   g_part[RR * 64];
__device__ int   g_csr_src[RR * EE];
__device__ float g_b0[(size_t)NN * DD];            // pre-norm layer output
__device__ float g_sum[DD];
__device__ float g_sumsq[DD];
__device__ float g_scale[DD];
__device__ float g_shift[DD];
__device__ int   g_bar;                            // last-block counter

// ---------------- CSR build (once per launch) ----------------
__global__ void count_kernel(const int* __restrict__ dst) {
    int r = blockIdx.y;
    int e = blockIdx.x * blockDim.x + threadIdx.x;
    if (e < EE) atomicAdd(&g_cnt[r * NN + dst[(size_t)r * EE + e]], 1);
}

__global__ void scan1_kernel() {
    int r = blockIdx.y;
    int b = blockIdx.x;
    int i = b * 1024 + threadIdx.x;
    __shared__ int s[1024];
    int v = (i < NN) ? g_cnt[r * NN + i] : 0;
    s[threadIdx.x] = v;
    __syncthreads();
    for (int o = 1; o < 1024; o <<= 1) {
        int t = (threadIdx.x >= o) ? s[threadIdx.x - o] : 0;
        __syncthreads();
        s[threadIdx.x] += t;
        __syncthreads();
    }
    if (i < NN) {
        g_off[r * (NN + 1) + i] = s[threadIdx.x] - v;
        g_cnt[r * NN + i] = 0;
    }
    if (threadIdx.x == 1023) g_part[r * 64 + b] = s[1023];
}

__global__ void scan2_kernel() {   // warp-scan of 49 partials per etype
    int w = threadIdx.x >> 5;
    int l = threadIdx.x & 31;
    if (w >= RR) return;
    int i0 = 2 * l, i1 = 2 * l + 1;
    int v0 = (i0 < SCAN_B) ? g_part[w * 64 + i0] : 0;
    int v1 = (i1 < SCAN_B) ? g_part[w * 64 + i1] : 0;
    int s = v0 + v1;
    int incl = s;
#pragma unroll
    for (int o = 1; o < 32; o <<= 1) {
        int t = __shfl_up_sync(0xFFFFFFFFu, incl, o);
        if (l >= o) incl += t;
    }
    int base = incl - s;
    if (i0 < SCAN_B) g_part[w * 64 + i0] = base;
    if (i1 < SCAN_B) g_part[w * 64 + i1] = base + v0;
    int total = __shfl_sync(0xFFFFFFFFu, incl, 31);
    if (l == 0) g_off[w * (NN + 1) + NN] = total;
}

__global__ void scan3_kernel() {
    int r = blockIdx.y;
    int b = blockIdx.x;
    int i = b * 1024 + threadIdx.x;
    if (i < NN) g_off[r * (NN + 1) + i] += g_part[r * 64 + b];
}

__global__ void fill_kernel(const int* __restrict__ src, const int* __restrict__ dst) {
    int r = blockIdx.y;
    int e = blockIdx.x * blockDim.x + threadIdx.x;
    if (e >= EE) return;
    int d = dst[(size_t)r * EE + e];
    int pos = g_off[r * (NN + 1) + d] + atomicAdd(&g_cnt[r * NN + d], 1);
    g_csr_src[(size_t)r * EE + pos] = src[(size_t)r * EE + e];
}

// ---------------- one-time W -> fp16 transposed (+ zero g_cnt) ----------------
__global__ void wconv_kernel(const float* __restrict__ Ws) {
    int mat = blockIdx.x;
    const float* W = Ws + (size_t)mat * DD * DD;
    __half* wt = g_wt + (size_t)mat * DD * DD;
    for (int idx = threadIdx.x; idx < DD * DD; idx += blockDim.x) {
        int k = idx >> 7, n = idx & 127;
        wt[n * DD + k] = __float2half(W[idx]);
    }
    int gt = blockIdx.x * blockDim.x + threadIdx.x;
    for (int i = gt; i < RR * NN; i += gridDim.x * blockDim.x) g_cnt[i] = 0;
}

// ---------------- x -> fp16 (layer 0 input) ----------------
__global__ void xconv_kernel(const float* __restrict__ x, __half* __restrict__ hn) {
    size_t i = (size_t)blockIdx.x * blockDim.x + threadIdx.x;
    if (i >= (size_t)NN * DD / 4) return;
    float4 v = ((const float4*)x)[i];
    __half2 h0 = __float22half2_rn(make_float2(v.x, v.y));
    __half2 h1 = __float22half2_rn(make_float2(v.z, v.w));
    uint2 w;
    w.x = *(uint32_t*)&h0; w.y = *(uint32_t*)&h1;
    ((uint2*)hn)[i] = w;
}

// ---------------- BN-apply -> fp16 (inter-layer) ----------------
__global__ void hnconv_kernel(const float* __restrict__ t, __half* __restrict__ hn) {
    size_t i = (size_t)blockIdx.x * blockDim.x + threadIdx.x;
    if (i >= (size_t)NN * DD / 4) return;
    int c4 = (int)(i & 31) * 4;
    float4 v = ((const float4*)t)[i];
    v.x = v.x * g_scale[c4 + 0] + g_shift[c4 + 0];
    v.y = v.y * g_scale[c4 + 1] + g_shift[c4 + 1];
    v.z = v.z * g_scale[c4 + 2] + g_shift[c4 + 2];
    v.w = v.w * g_scale[c4 + 3] + g_shift[c4 + 3];
    __half2 h0 = __float22half2_rn(make_float2(v.x, v.y));
    __half2 h1 = __float22half2_rn(make_float2(v.z, v.w));
    uint2 w;
    w.x = *(uint32_t*)&h0; w.y = *(uint32_t*)&h1;
    ((uint2*)hn)[i] = w;
}

__global__ void bnnorm_kernel(const float* __restrict__ t, float* __restrict__ outp) {
    size_t i = (size_t)blockIdx.x * blockDim.x + threadIdx.x;
    if (i >= (size_t)NN * DD / 4) return;
    int c4 = (int)(i & 31) * 4;
    float4 v = ((const float4*)t)[i];
    v.x = v.x * g_scale[c4 + 0] + g_shift[c4 + 0];
    v.y = v.y * g_scale[c4 + 1] + g_shift[c4 + 1];
    v.z = v.z * g_scale[c4 + 2] + g_shift[c4 + 2];
    v.w = v.w * g_scale[c4 + 3] + g_shift[c4 + 3];
    ((float4*)outp)[i] = v;
}

// ---------------- fp16 HMMA GEMM z = hn @ W  + el/er epilogue ----------------
#define PAD 136   // smem pitch in halves (conflict-free)

#define MMA_F16(c, a, b0, b1)                                                 \
    asm volatile(                                                             \
        "mma.sync.aligned.m16n8k16.row.col.f32.f16.f16.f32 "                  \
        "{%0,%1,%2,%3},{%4,%5,%6,%7},{%8,%9},{%0,%1,%2,%3};"                  \
        : "+f"((c)[0]), "+f"((c)[1]), "+f"((c)[2]), "+f"((c)[3])              \
        : "r"((a)[0]), "r"((a)[1]), "r"((a)[2]), "r"((a)[3]),                 \
          "r"(b0), "r"(b1))

#define LDMX4(r0, r1, r2, r3, addr)                                           \
    asm volatile(                                                             \
        "ldmatrix.sync.aligned.m8n8.x4.shared.b16 {%0,%1,%2,%3}, [%4];"       \
        : "=r"(r0), "=r"(r1), "=r"(r2), "=r"(r3) : "r"(addr))

__global__ __launch_bounds__(256) void gemm_hmma_kernel(
    const __half* __restrict__ hn,       // [NN, DD] fp16 normalized
    const __half* __restrict__ wt_layer, // [RR, DD(n), DD(k)] fp16 transposed
    const float* __restrict__ al_layer,
    const float* __restrict__ ar_layer)
{
    extern __shared__ __half sm[];
    __half* As = sm;               // [128][PAD]
    __half* Bs = sm + 128 * PAD;   // [128][PAD]
    __shared__ float s_al[DD], s_ar[DD];
    __shared__ float s_el[128][2], s_er[128][2];

    int r = blockIdx.y;
    int rowBase = blockIdx.x * 128;
    int tid  = threadIdx.x;
    int lane = tid & 31;
    int wid  = tid >> 5;
    int mw   = wid >> 1;   // 0..3
    int nw   = wid & 1;    // 0..1
    int l8 = lane & 7;
    int lj = lane >> 3;

    if (tid < DD) {
        s_al[tid] = al_layer[(size_t)r * DD + tid];
        s_ar[tid] = ar_layer[(size_t)r * DD + tid];
    }

    // ---- stage A: fp16 uint4 copies (clamped rows; stores guarded later) ----
    {
        const uint4* hp = (const uint4*)hn;
        for (int u = tid; u < 128 * 16; u += 256) {
            int row = u >> 4;
            int k8  = (u & 15) * 8;
            int grow = rowBase + row;
            if (grow > NN - 1) grow = NN - 1;
            *(uint4*)(As + row * PAD + k8) = hp[(size_t)grow * 16 + (u & 15)];
        }
    }
    // ---- stage B ----
    {
        const uint4* wt = (const uint4*)(wt_layer + (size_t)r * DD * DD);
        for (int u = tid; u < 128 * 16; u += 256) {
            int n  = u >> 4;
            int k8 = (u & 15) * 8;
            *(uint4*)(Bs + n * PAD + k8) = wt[u];
        }
    }
    __syncthreads();

    float acc[2][8][4];
#pragma unroll
    for (int mt = 0; mt < 2; mt++)
#pragma unroll
        for (int nt = 0; nt < 8; nt++)
#pragma unroll
            for (int c = 0; c < 4; c++) acc[mt][nt][c] = 0.f;

#pragma unroll
    for (int k16 = 0; k16 < 8; k16++) {
        int kk = k16 * 16;
        uint32_t a[2][4];
#pragma unroll
        for (int mt = 0; mt < 2; mt++) {
            const __half* pa = As + (mw * 32 + mt * 16 + l8 + 8 * (lj & 1)) * PAD
                                  + kk + 8 * (lj >> 1);
            LDMX4(a[mt][0], a[mt][1], a[mt][2], a[mt][3],
                  (uint32_t)__cvta_generic_to_shared(pa));
        }
#pragma unroll
        for (int np = 0; np < 4; np++) {   // each covers nt = 2np, 2np+1
            const __half* pb = Bs + (nw * 64 + np * 16 + l8 + 8 * (lj >> 1)) * PAD
                                  + kk + 8 * (lj & 1);
            uint32_t b0, b1, b2, b3;
            LDMX4(b0, b1, b2, b3, (uint32_t)__cvta_generic_to_shared(pb));
#pragma unroll
            for (int mt = 0; mt < 2; mt++) {
                MMA_F16(acc[mt][2 * np],     a[mt], b0, b1);
                MMA_F16(acc[mt][2 * np + 1], a[mt], b2, b3);
            }
        }
    }

    // ---- epilogue: z store (fp16) + attention dots (fp32) ----
    __half* zr = g_z + (size_t)r * NN * DD;
    float pl[2][2] = {{0.f, 0.f}, {0.f, 0.f}};
    float pr[2][2] = {{0.f, 0.f}, {0.f, 0.f}};
#pragma unroll
    for (int mt = 0; mt < 2; mt++) {
        int row0 = rowBase + mw * 32 + mt * 16 + (lane >> 2);
        int row1 = row0 + 8;
#pragma unroll
        for (int nt = 0; nt < 8; nt++) {
            int nc = nw * 64 + nt * 8 + 2 * (lane & 3);
            float al0 = s_al[nc], al1 = s_al[nc + 1];
            float ar0 = s_ar[nc], ar1 = s_ar[nc + 1];
            pl[mt][0] += acc[mt][nt][0] * al0 + acc[mt][nt][1] * al1;
            pr[mt][0] += acc[mt][nt][0] * ar0 + acc[mt][nt][1] * ar1;
            pl[mt][1] += acc[mt][nt][2] * al0 + acc[mt][nt][3] * al1;
            pr[mt][1] += acc[mt][nt][2] * ar0 + acc[mt][nt][3] * ar1;
            if (row0 < NN)
                *(__half2*)(zr + (size_t)row0 * DD + nc) =
                    __float22half2_rn(make_float2(acc[mt][nt][0], acc[mt][nt][1]));
            if (row1 < NN)
                *(__half2*)(zr + (size_t)row1 * DD + nc) =
                    __float22half2_rn(make_float2(acc[mt][nt][2], acc[mt][nt][3]));
        }
    }
#pragma unroll
    for (int mt = 0; mt < 2; mt++)
#pragma unroll
        for (int i = 0; i < 2; i++) {
#pragma unroll
            for (int o = 1; o <= 2; o <<= 1) {
                pl[mt][i] += __shfl_xor_sync(0xFFFFFFFFu, pl[mt][i], o);
                pr[mt][i] += __shfl_xor_sync(0xFFFFFFFFu, pr[mt][i], o);
            }
            if ((lane & 3) == 0) {
                int rl = mw * 32 + mt * 16 + (lane >> 2) + 8 * i;
                s_el[rl][nw] = pl[mt][i];
                s_er[rl][nw] = pr[mt][i];
            }
        }
    __syncthreads();
    if (tid < 128) {
        int g = rowBase + tid;
        if (g < NN) {
            g_el[r * NN + g] = s_el[tid][0] + s_el[tid][1];
            g_er[r * NN + g] = s_er[tid][0] + s_er[tid][1];
        }
    }
}

// ---------------- per-layer edge softmax weights (alpha) ----------------
__global__ void edgew_kernel() {
    int r = blockIdx.y;
    int n = blockIdx.x * blockDim.x + threadIdx.x;
    if (n >= NN) return;
    int b0 = g_off[r * (NN + 1) + n];
    int b1 = g_off[r * (NN + 1) + n + 1];
    if (b0 >= b1) return;
    float ern = g_er[r * NN + n];
    const float* elr = g_el + r * NN;
    const int*   cs  = g_csr_src + (size_t)r * EE;
    float* ax = g_alpha + (size_t)r * EE;
    float ssum = 0.f;
    for (int idx = b0; idx < b1; ++idx) {   // pass 1: exp + store
        float v = elr[cs[idx]] + ern;
        v = v > 0.f ? v : 0.2f * v;
        float e = __expf(v);
        ax[idx] = e;
        ssum += e;
    }
    float inv = 1.f / ssum;
    for (int idx = b0; idx < b1; ++idx)     // pass 2: scale in place
        ax[idx] *= inv;
}

// ---------------- fused aggregation + BN stats + BN finalize ----------------
__global__ __launch_bounds__(256) void heavy_all_kernel(
    const __half* __restrict__ hn,        // [NN, DD] fp16 normalized input
    const float* __restrict__ bias_layer, // [RR, DD]
    float* __restrict__ t,
    int dorelu,
    const float* __restrict__ gamma,
    const float* __restrict__ beta)
{
    int lane = threadIdx.x & 31;
    int wid  = threadIdx.x >> 5;

    float4 bv[RR];
#pragma unroll
    for (int r = 0; r < RR; r++)
        bv[r] = *(const float4*)(bias_layer + r * DD + lane * 4);

    float4 bsum = make_float4(0.f, 0.f, 0.f, 0.f);
    float4 bsq  = make_float4(0.f, 0.f, 0.f, 0.f);

    for (int n = blockIdx.x * 8 + wid; n < NN; n += gridDim.x * 8) {
        uint2 hw = *(const uint2*)(hn + (size_t)n * DD + lane * 4);
        __half2 hq0 = *(__half2*)&hw.x;
        __half2 hq1 = *(__half2*)&hw.y;
        float2 hf0 = __half22float2(hq0);
        float2 hf1 = __half22float2(hq1);
        float4 hv = make_float4(hf0.x, hf0.y, hf1.x, hf1.y);

        float4 tot = make_float4(0.f, 0.f, 0.f, 0.f);
#pragma unroll
        for (int r = 0; r < RR; r++) {
            int b0 = g_off[r * (NN + 1) + n];
            int b1 = g_off[r * (NN + 1) + n + 1];
            const int*   cs = g_csr_src + (size_t)r * EE;
            const float* ax = g_alpha + (size_t)r * EE;
            const __half2* zp = (const __half2*)g_z + (size_t)r * NN * (DD / 2);

            // unroll x2 with independent accumulators (doubles gather MLP)
            float4 acc0 = make_float4(0.f, 0.f, 0.f, 0.f);
            float4 acc1 = make_float4(0.f, 0.f, 0.f, 0.f);
            int idx = b0;
            for (; idx + 1 < b1; idx += 2) {
                int   s0 = cs[idx],     s1 = cs[idx + 1];
                float a0 = ax[idx],     a1 = ax[idx + 1];
                uint2 w0 = *(const uint2*)(zp + (size_t)s0 * (DD / 2) + lane * 2);
                uint2 w1 = *(const uint2*)(zp + (size_t)s1 * (DD / 2) + lane * 2);
                float2 f00 = __half22float2(*(__half2*)&w0.x);
                float2 f01 = __half22float2(*(__half2*)&w0.y);
                float2 f10 = __half22float2(*(__half2*)&w1.x);
                float2 f11 = __half22float2(*(__half2*)&w1.y);
                acc0.x += a0 * f00.x; acc0.y += a0 * f00.y;
                acc0.z += a0 * f01.x; acc0.w += a0 * f01.y;
                acc1.x += a1 * f10.x; acc1.y += a1 * f10.y;
                acc1.z += a1 * f11.x; acc1.w += a1 * f11.y;
            }
            if (idx < b1) {
                int   s0 = cs[idx];
                float a0 = ax[idx];
                uint2 w0 = *(const uint2*)(zp + (size_t)s0 * (DD / 2) + lane * 2);
                float2 f00 = __half22float2(*(__half2*)&w0.x);
                float2 f01 = __half22float2(*(__half2*)&w0.y);
                acc0.x += a0 * f00.x; acc0.y += a0 * f00.y;
                acc0.z += a0 * f01.x; acc0.w += a0 * f01.y;
            }
            float4 v4 = make_float4(acc0.x + acc1.x + hv.x + bv[r].x,
                                    acc0.y + acc1.y + hv.y + bv[r].y,
                                    acc0.z + acc1.z + hv.z + bv[r].z,
                                    acc0.w + acc1.w + hv.w + bv[r].w);
            if (dorelu) {
                v4.x = fmaxf(v4.x, 0.f); v4.y = fmaxf(v4.y, 0.f);
                v4.z = fmaxf(v4.z, 0.f); v4.w = fmaxf(v4.w, 0.f);
            }
            tot.x += v4.x; tot.y += v4.y; tot.z += v4.z; tot.w += v4.w;
        }
        *(float4*)(t + (size_t)n * DD + lane * 4) = tot;
        bsum.x += tot.x; bsum.y += tot.y; bsum.z += tot.z; bsum.w += tot.w;
        bsq.x += tot.x * tot.x; bsq.y += tot.y * tot.y;
        bsq.z += tot.z * tot.z; bsq.w += tot.w * tot.w;
    }

    // block-level BN stat reduction
    __shared__ float sb[8][DD], sb2[8][DD];
    *(float4*)(&sb[wid][lane * 4])  = bsum;
    *(float4*)(&sb2[wid][lane * 4]) = bsq;
    __syncthreads();
    int tid = threadIdx.x;
    if (tid < DD) {
        float s = 0.f;
#pragma unroll
        for (int w = 0; w < 8; w++) s += sb[w][tid];
        atomicAdd(&g_sum[tid], s);
    } else {
        int col = tid - DD;
        float s2 = 0.f;
#pragma unroll
        for (int w = 0; w < 8; w++) s2 += sb2[w][col];
        atomicAdd(&g_sumsq[col], s2);
    }

    // last block finalizes BN affine (and resets for replay determinism)
    __shared__ int s_last;
    __threadfence();
    if (tid == 0) s_last = (atomicAdd(&g_bar, 1) == (int)gridDim.x - 1);
    __syncthreads();
    if (s_last) {
        if (tid < DD) {
            float invN = 1.f / (float)NN;
            float mu  = g_sum[tid] * invN;
            float var = g_sumsq[tid] * invN - mu * mu;
            float rs  = rsqrtf(var + 1e-5f);
            float g   = gamma[tid];
            g_scale[tid] = rs * g;
            g_shift[tid] = beta[tid] - mu * rs * g;
            g_sum[tid] = 0.f;
            g_sumsq[tid] = 0.f;
        }
        if (tid == 0) g_bar = 0;
    }
}

// ---------------- launcher ----------------
extern "C" void kernel_launch(void* const* d_in, const int* in_sizes, int n_in,
                              void* d_out, int out_size) {
    const float* x     = (const float*)d_in[0];
    const int*   src   = (const int*)d_in[1];
    const int*   dst   = (const int*)d_in[2];
    const float* Ws    = (const float*)d_in[3];
    const float* attnl = (const float*)d_in[4];
    const float* attnr = (const float*)d_in[5];
    const float* bias  = (const float*)d_in[6];
    const float* gamma = (const float*)d_in[7];
    const float* beta  = (const float*)d_in[8];
    float* out = (float*)d_out;

    float* p_b0 = nullptr;
    __half *p_wt = nullptr, *p_hn = nullptr;
    cudaGetSymbolAddress((void**)&p_b0, g_b0);
    cudaGetSymbolAddress((void**)&p_wt, g_wt);
    cudaGetSymbolAddress((void**)&p_hn, g_hn);

    const int SMEM_BYTES = 2 * 128 * PAD * (int)sizeof(__half);  // 69632
    cudaFuncSetAttribute(gemm_hmma_kernel,
                         cudaFuncAttributeMaxDynamicSharedMemorySize, SMEM_BYTES);

    dim3 gemm_grid((NN + 127) / 128, RR);
    dim3 edge_grid((EE + 255) / 256, RR);
    dim3 scan_grid(SCAN_B, RR);
    dim3 node_grid((NN + 255) / 256, RR);
    int heavy_blocks = 1184;
    int norm_blocks  = ((NN * DD / 4) + 255) / 256;

    // ---- setup ----
    wconv_kernel<<<LL * RR, 256>>>(Ws);                 // #1 (also zeroes g_cnt)
    xconv_kernel<<<norm_blocks, 256>>>(x, p_hn);        // #2
    count_kernel<<<edge_grid, 256>>>(dst);              // #3
    gemm_hmma_kernel<<<gemm_grid, 256, SMEM_BYTES>>>(   // #4: layer-0 GEMM
        p_hn, p_wt, attnl, attnr);
    scan1_kernel<<<scan_grid, 1024>>>();                // #5
    scan2_kernel<<<1, 96>>>();                          // #6
    scan3_kernel<<<scan_grid, 1024>>>();                // #7
    fill_kernel<<<edge_grid, 256>>>(src, dst);          // #8

    for (int i = 0; i < LL; i++) {
        float* tbuf = (i < LL - 1) ? p_b0 : out;

        if (i > 0) {
            gemm_hmma_kernel<<<gemm_grid, 256, SMEM_BYTES>>>(
                p_hn,
                p_wt  + (size_t)i * RR * DD * DD,
                attnl + (size_t)i * RR * DD,
                attnr + (size_t)i * RR * DD);
        }
        edgew_kernel<<<node_grid, 256>>>();
        heavy_all_kernel<<<heavy_blocks, 256>>>(
            p_hn,
            bias + (size_t)i * RR * DD,
            tbuf, /*dorelu=*/(i < LL - 1),
            gamma + (size_t)i * DD,
            beta  + (size_t)i * DD);
        if (i < LL - 1)
            hnconv_kernel<<<norm_blocks, 256>>>(tbuf, p_hn);
        else
            bnnorm_kernel<<<norm_blocks, 256>>>(out, out);
    }
}

// round 17
// speedup vs baseline: 1.1346x; 1.0167x over previous
#include <cuda_runtime.h>
#include <cuda_fp16.h>
#include <math.h>
#include <stdint.h>

#define NN 50000
#define RR 3
#define EE 600000
#define DD 128
#define LL 3
#define SCAN_B 49   // ceil(50000/1024)

// ---------------- scratch (device globals) ----------------
__device__ __half g_z[(size_t)RR * NN * DD];       // projected features, fp16
__device__ __half g_wt[(size_t)LL * RR * DD * DD]; // W fp16, transposed [n][k]
__device__ __half g_hn[(size_t)NN * DD];           // normalized h, fp16
__device__ float g_el[RR * NN];
__device__ float g_er[RR * NN];
__device__ float g_alpha[(size_t)RR * EE];         // per-edge softmax weight
__device__ int   g_cnt[RR * NN];
__device__ int   g_off[RR * (NN + 1)];
__device__ int   g_part[RR * 64];
__device__ int   g_csr_src[RR * EE];
__device__ float g_b0[(size_t)NN * DD];            // pre-norm layer output
__device__ float g_sum[DD];
__device__ float g_sumsq[DD];
__device__ float g_scale[DD];
__device__ float g_shift[DD];
__device__ int   g_bar;                            // last-block counter

// ---------------- CSR build (once per launch) ----------------
__global__ void count_kernel(const int* __restrict__ dst) {
    int r = blockIdx.y;
    int e = blockIdx.x * blockDim.x + threadIdx.x;
    if (e < EE) atomicAdd(&g_cnt[r * NN + dst[(size_t)r * EE + e]], 1);
}

__global__ void scan1_kernel() {
    int r = blockIdx.y;
    int b = blockIdx.x;
    int i = b * 1024 + threadIdx.x;
    __shared__ int s[1024];
    int v = (i < NN) ? g_cnt[r * NN + i] : 0;
    s[threadIdx.x] = v;
    __syncthreads();
    for (int o = 1; o < 1024; o <<= 1) {
        int t = (threadIdx.x >= o) ? s[threadIdx.x - o] : 0;
        __syncthreads();
        s[threadIdx.x] += t;
        __syncthreads();
    }
    if (i < NN) {
        g_off[r * (NN + 1) + i] = s[threadIdx.x] - v;
        g_cnt[r * NN + i] = 0;
    }
    if (threadIdx.x == 1023) g_part[r * 64 + b] = s[1023];   // block total
}

// scan3 now also computes the per-block prefix of partials (scan2 folded in)
__global__ void scan3_kernel() {
    int r = blockIdx.y;
    int b = blockIdx.x;
    __shared__ int s_base, s_total;
    if (threadIdx.x < 32) {
        int l = threadIdx.x;
        int i0 = 2 * l, i1 = 2 * l + 1;
        int v0 = (i0 < SCAN_B) ? g_part[r * 64 + i0] : 0;
        int v1 = (i1 < SCAN_B) ? g_part[r * 64 + i1] : 0;
        int pair = v0 + v1;
        int incl = pair;
#pragma unroll
        for (int o = 1; o < 32; o <<= 1) {
            int t = __shfl_up_sync(0xFFFFFFFFu, incl, o);
            if (l >= o) incl += t;
        }
        // exclusive prefix at pair granularity
        int excl_pair = incl - pair;
        // base for block b: sum of partials [0, b)
        int pb = b >> 1;
        int base_p = __shfl_sync(0xFFFFFFFFu, excl_pair, pb);
        int v0b    = __shfl_sync(0xFFFFFFFFu, v0, pb);
        if (l == 0) {
            s_base  = base_p + ((b & 1) ? v0b : 0);
            s_total = __shfl_sync(0xFFFFFFFFu, incl, 31);
        } else {
            __shfl_sync(0xFFFFFFFFu, incl, 31);  // keep shfl convergent
        }
    }
    __syncthreads();
    int base = s_base;
    int i = b * 1024 + threadIdx.x;
    if (i < NN) g_off[r * (NN + 1) + i] += base;
    if (i == NN - 1) g_off[r * (NN + 1) + NN] = s_total;
}

__global__ void fill_kernel(const int* __restrict__ src, const int* __restrict__ dst) {
    int r = blockIdx.y;
    int e = blockIdx.x * blockDim.x + threadIdx.x;
    if (e >= EE) return;
    int d = dst[(size_t)r * EE + e];
    int pos = g_off[r * (NN + 1) + d] + atomicAdd(&g_cnt[r * NN + d], 1);
    g_csr_src[(size_t)r * EE + pos] = src[(size_t)r * EE + e];
}

// ---------------- one-time W -> fp16 transposed (+ zero g_cnt) ----------------
__global__ void wconv_kernel(const float* __restrict__ Ws) {
    int mat = blockIdx.x;
    const float* W = Ws + (size_t)mat * DD * DD;
    __half* wt = g_wt + (size_t)mat * DD * DD;
    for (int idx = threadIdx.x; idx < DD * DD; idx += blockDim.x) {
        int k = idx >> 7, n = idx & 127;
        wt[n * DD + k] = __float2half(W[idx]);
    }
    int gt = blockIdx.x * blockDim.x + threadIdx.x;
    for (int i = gt; i < RR * NN; i += gridDim.x * blockDim.x) g_cnt[i] = 0;
}

// ---------------- x -> fp16 (layer 0 input) ----------------
__global__ void xconv_kernel(const float* __restrict__ x, __half* __restrict__ hn) {
    size_t i = (size_t)blockIdx.x * blockDim.x + threadIdx.x;
    if (i >= (size_t)NN * DD / 4) return;
    float4 v = ((const float4*)x)[i];
    __half2 h0 = __float22half2_rn(make_float2(v.x, v.y));
    __half2 h1 = __float22half2_rn(make_float2(v.z, v.w));
    uint2 w;
    w.x = *(uint32_t*)&h0; w.y = *(uint32_t*)&h1;
    ((uint2*)hn)[i] = w;
}

// ---------------- BN-apply -> fp16 (inter-layer) ----------------
__global__ void hnconv_kernel(const float* __restrict__ t, __half* __restrict__ hn) {
    size_t i = (size_t)blockIdx.x * blockDim.x + threadIdx.x;
    if (i >= (size_t)NN * DD / 4) return;
    int c4 = (int)(i & 31) * 4;
    float4 v = ((const float4*)t)[i];
    v.x = v.x * g_scale[c4 + 0] + g_shift[c4 + 0];
    v.y = v.y * g_scale[c4 + 1] + g_shift[c4 + 1];
    v.z = v.z * g_scale[c4 + 2] + g_shift[c4 + 2];
    v.w = v.w * g_scale[c4 + 3] + g_shift[c4 + 3];
    __half2 h0 = __float22half2_rn(make_float2(v.x, v.y));
    __half2 h1 = __float22half2_rn(make_float2(v.z, v.w));
    uint2 w;
    w.x = *(uint32_t*)&h0; w.y = *(uint32_t*)&h1;
    ((uint2*)hn)[i] = w;
}

__global__ void bnnorm_kernel(const float* __restrict__ t, float* __restrict__ outp) {
    size_t i = (size_t)blockIdx.x * blockDim.x + threadIdx.x;
    if (i >= (size_t)NN * DD / 4) return;
    int c4 = (int)(i & 31) * 4;
    float4 v = ((const float4*)t)[i];
    v.x = v.x * g_scale[c4 + 0] + g_shift[c4 + 0];
    v.y = v.y * g_scale[c4 + 1] + g_shift[c4 + 1];
    v.z = v.z * g_scale[c4 + 2] + g_shift[c4 + 2];
    v.w = v.w * g_scale[c4 + 3] + g_shift[c4 + 3];
    ((float4*)outp)[i] = v;
}

// ---------------- fp16 HMMA GEMM z = hn @ W  + el/er epilogue ----------------
#define PAD 136   // smem pitch in halves (conflict-free)

#define MMA_F16(c, a, b0, b1)                                                 \
    asm volatile(                                                             \
        "mma.sync.aligned.m16n8k16.row.col.f32.f16.f16.f32 "                  \
        "{%0,%1,%2,%3},{%4,%5,%6,%7},{%8,%9},{%0,%1,%2,%3};"                  \
        : "+f"((c)[0]), "+f"((c)[1]), "+f"((c)[2]), "+f"((c)[3])              \
        : "r"((a)[0]), "r"((a)[1]), "r"((a)[2]), "r"((a)[3]),                 \
          "r"(b0), "r"(b1))

#define LDMX4(r0, r1, r2, r3, addr)                                           \
    asm volatile(                                                             \
        "ldmatrix.sync.aligned.m8n8.x4.shared.b16 {%0,%1,%2,%3}, [%4];"       \
        : "=r"(r0), "=r"(r1), "=r"(r2), "=r"(r3) : "r"(addr))

__global__ __launch_bounds__(256) void gemm_hmma_kernel(
    const __half* __restrict__ hn,       // [NN, DD] fp16 normalized
    const __half* __restrict__ wt_layer, // [RR, DD(n), DD(k)] fp16 transposed
    const float* __restrict__ al_layer,
    const float* __restrict__ ar_layer)
{
    extern __shared__ __half sm[];
    __half* As = sm;               // [128][PAD]
    __half* Bs = sm + 128 * PAD;   // [128][PAD]
    __shared__ float s_al[DD], s_ar[DD];
    __shared__ float s_el[128][2], s_er[128][2];

    int r = blockIdx.y;
    int rowBase = blockIdx.x * 128;
    int tid  = threadIdx.x;
    int lane = tid & 31;
    int wid  = tid >> 5;
    int mw   = wid >> 1;   // 0..3
    int nw   = wid & 1;    // 0..1
    int l8 = lane & 7;
    int lj = lane >> 3;

    if (tid < DD) {
        s_al[tid] = al_layer[(size_t)r * DD + tid];
        s_ar[tid] = ar_layer[(size_t)r * DD + tid];
    }

    // ---- stage A: fp16 uint4 copies (clamped rows; stores guarded later) ----
    {
        const uint4* hp = (const uint4*)hn;
        for (int u = tid; u < 128 * 16; u += 256) {
            int row = u >> 4;
            int k8  = (u & 15) * 8;
            int grow = rowBase + row;
            if (grow > NN - 1) grow = NN - 1;
            *(uint4*)(As + row * PAD + k8) = hp[(size_t)grow * 16 + (u & 15)];
        }
    }
    // ---- stage B ----
    {
        const uint4* wt = (const uint4*)(wt_layer + (size_t)r * DD * DD);
        for (int u = tid; u < 128 * 16; u += 256) {
            int n  = u >> 4;
            int k8 = (u & 15) * 8;
            *(uint4*)(Bs + n * PAD + k8) = wt[u];
        }
    }
    __syncthreads();

    float acc[2][8][4];
#pragma unroll
    for (int mt = 0; mt < 2; mt++)
#pragma unroll
        for (int nt = 0; nt < 8; nt++)
#pragma unroll
            for (int c = 0; c < 4; c++) acc[mt][nt][c] = 0.f;

#pragma unroll
    for (int k16 = 0; k16 < 8; k16++) {
        int kk = k16 * 16;
        uint32_t a[2][4];
#pragma unroll
        for (int mt = 0; mt < 2; mt++) {
            const __half* pa = As + (mw * 32 + mt * 16 + l8 + 8 * (lj & 1)) * PAD
                                  + kk + 8 * (lj >> 1);
            LDMX4(a[mt][0], a[mt][1], a[mt][2], a[mt][3],
                  (uint32_t)__cvta_generic_to_shared(pa));
        }
#pragma unroll
        for (int np = 0; np < 4; np++) {   // each covers nt = 2np, 2np+1
            const __half* pb = Bs + (nw * 64 + np * 16 + l8 + 8 * (lj >> 1)) * PAD
                                  + kk + 8 * (lj & 1);
            uint32_t b0, b1, b2, b3;
            LDMX4(b0, b1, b2, b3, (uint32_t)__cvta_generic_to_shared(pb));
#pragma unroll
            for (int mt = 0; mt < 2; mt++) {
                MMA_F16(acc[mt][2 * np],     a[mt], b0, b1);
                MMA_F16(acc[mt][2 * np + 1], a[mt], b2, b3);
            }
        }
    }

    // ---- epilogue: z store (fp16) + attention dots (fp32) ----
    __half* zr = g_z + (size_t)r * NN * DD;
    float pl[2][2] = {{0.f, 0.f}, {0.f, 0.f}};
    float pr[2][2] = {{0.f, 0.f}, {0.f, 0.f}};
#pragma unroll
    for (int mt = 0; mt < 2; mt++) {
        int row0 = rowBase + mw * 32 + mt * 16 + (lane >> 2);
        int row1 = row0 + 8;
#pragma unroll
        for (int nt = 0; nt < 8; nt++) {
            int nc = nw * 64 + nt * 8 + 2 * (lane & 3);
            float al0 = s_al[nc], al1 = s_al[nc + 1];
            float ar0 = s_ar[nc], ar1 = s_ar[nc + 1];
            pl[mt][0] += acc[mt][nt][0] * al0 + acc[mt][nt][1] * al1;
            pr[mt][0] += acc[mt][nt][0] * ar0 + acc[mt][nt][1] * ar1;
            pl[mt][1] += acc[mt][nt][2] * al0 + acc[mt][nt][3] * al1;
            pr[mt][1] += acc[mt][nt][2] * ar0 + acc[mt][nt][3] * ar1;
            if (row0 < NN)
                *(__half2*)(zr + (size_t)row0 * DD + nc) =
                    __float22half2_rn(make_float2(acc[mt][nt][0], acc[mt][nt][1]));
            if (row1 < NN)
                *(__half2*)(zr + (size_t)row1 * DD + nc) =
                    __float22half2_rn(make_float2(acc[mt][nt][2], acc[mt][nt][3]));
        }
    }
#pragma unroll
    for (int mt = 0; mt < 2; mt++)
#pragma unroll
        for (int i = 0; i < 2; i++) {
#pragma unroll
            for (int o = 1; o <= 2; o <<= 1) {
                pl[mt][i] += __shfl_xor_sync(0xFFFFFFFFu, pl[mt][i], o);
                pr[mt][i] += __shfl_xor_sync(0xFFFFFFFFu, pr[mt][i], o);
            }
            if ((lane & 3) == 0) {
                int rl = mw * 32 + mt * 16 + (lane >> 2) + 8 * i;
                s_el[rl][nw] = pl[mt][i];
                s_er[rl][nw] = pr[mt][i];
            }
        }
    __syncthreads();
    if (tid < 128) {
        int g = rowBase + tid;
        if (g < NN) {
            g_el[r * NN + g] = s_el[tid][0] + s_el[tid][1];
            g_er[r * NN + g] = s_er[tid][0] + s_er[tid][1];
        }
    }
}

// ---------------- per-layer edge softmax weights: warp per node ----------------
__global__ __launch_bounds__(256) void edgew_kernel() {
    int r = blockIdx.y;
    int wid  = threadIdx.x >> 5;
    int lane = threadIdx.x & 31;
    int n = blockIdx.x * 8 + wid;
    if (n >= NN) return;
    int b0 = g_off[r * (NN + 1) + n];
    int b1 = g_off[r * (NN + 1) + n + 1];
    if (b0 >= b1) return;
    float ern = g_er[r * NN + n];
    const float* elr = g_el + r * NN;
    const int*   cs  = g_csr_src + (size_t)r * EE;
    float* ax = g_alpha + (size_t)r * EE;

    // first chunk kept in registers (covers degree <= 32, the common case)
    int idx0 = b0 + lane;
    float e0 = 0.f;
    if (idx0 < b1) {
        float v = elr[cs[idx0]] + ern;
        v = v > 0.f ? v : 0.2f * v;
        e0 = __expf(v);
    }
    float ssum = e0;
    // rare extra chunks: store unnormalized, rescale after
    for (int base = b0 + 32; base < b1; base += 32) {
        int idx = base + lane;
        float e = 0.f;
        if (idx < b1) {
            float v = elr[cs[idx]] + ern;
            v = v > 0.f ? v : 0.2f * v;
            e = __expf(v);
            ax[idx] = e;
        }
        ssum += e;
    }
#pragma unroll
    for (int o = 16; o >= 1; o >>= 1)
        ssum += __shfl_xor_sync(0xFFFFFFFFu, ssum, o);
    float inv = 1.f / ssum;
    if (idx0 < b1) ax[idx0] = e0 * inv;
    for (int base = b0 + 32; base < b1; base += 32) {
        int idx = base + lane;
        if (idx < b1) ax[idx] *= inv;
    }
}

// ---------------- fused aggregation + BN stats + BN finalize ----------------
__global__ __launch_bounds__(256) void heavy_all_kernel(
    const __half* __restrict__ hn,        // [NN, DD] fp16 normalized input
    const float* __restrict__ bias_layer, // [RR, DD]
    float* __restrict__ t,
    int dorelu,
    const float* __restrict__ gamma,
    const float* __restrict__ beta)
{
    int lane = threadIdx.x & 31;
    int wid  = threadIdx.x >> 5;

    float4 bv[RR];
#pragma unroll
    for (int r = 0; r < RR; r++)
        bv[r] = *(const float4*)(bias_layer + r * DD + lane * 4);

    float4 bsum = make_float4(0.f, 0.f, 0.f, 0.f);
    float4 bsq  = make_float4(0.f, 0.f, 0.f, 0.f);

    for (int n = blockIdx.x * 8 + wid; n < NN; n += gridDim.x * 8) {
        uint2 hw = *(const uint2*)(hn + (size_t)n * DD + lane * 4);
        __half2 hq0 = *(__half2*)&hw.x;
        __half2 hq1 = *(__half2*)&hw.y;
        float2 hf0 = __half22float2(hq0);
        float2 hf1 = __half22float2(hq1);
        float4 hv = make_float4(hf0.x, hf0.y, hf1.x, hf1.y);

        float4 tot = make_float4(0.f, 0.f, 0.f, 0.f);
#pragma unroll
        for (int r = 0; r < RR; r++) {
            int b0 = g_off[r * (NN + 1) + n];
            int b1 = g_off[r * (NN + 1) + n + 1];
            const int*   cs = g_csr_src + (size_t)r * EE;
            const float* ax = g_alpha + (size_t)r * EE;
            const __half2* zp = (const __half2*)g_z + (size_t)r * NN * (DD / 2);

            // unroll x2 with independent accumulators (doubles gather MLP)
            float4 acc0 = make_float4(0.f, 0.f, 0.f, 0.f);
            float4 acc1 = make_float4(0.f, 0.f, 0.f, 0.f);
            int idx = b0;
            for (; idx + 1 < b1; idx += 2) {
                int   s0 = cs[idx],     s1 = cs[idx + 1];
                float a0 = ax[idx],     a1 = ax[idx + 1];
                uint2 w0 = *(const uint2*)(zp + (size_t)s0 * (DD / 2) + lane * 2);
                uint2 w1 = *(const uint2*)(zp + (size_t)s1 * (DD / 2) + lane * 2);
                float2 f00 = __half22float2(*(__half2*)&w0.x);
                float2 f01 = __half22float2(*(__half2*)&w0.y);
                float2 f10 = __half22float2(*(__half2*)&w1.x);
                float2 f11 = __half22float2(*(__half2*)&w1.y);
                acc0.x += a0 * f00.x; acc0.y += a0 * f00.y;
                acc0.z += a0 * f01.x; acc0.w += a0 * f01.y;
                acc1.x += a1 * f10.x; acc1.y += a1 * f10.y;
                acc1.z += a1 * f11.x; acc1.w += a1 * f11.y;
            }
            if (idx < b1) {
                int   s0 = cs[idx];
                float a0 = ax[idx];
                uint2 w0 = *(const uint2*)(zp + (size_t)s0 * (DD / 2) + lane * 2);
                float2 f00 = __half22float2(*(__half2*)&w0.x);
                float2 f01 = __half22float2(*(__half2*)&w0.y);
                acc0.x += a0 * f00.x; acc0.y += a0 * f00.y;
                acc0.z += a0 * f01.x; acc0.w += a0 * f01.y;
            }
            float4 v4 = make_float4(acc0.x + acc1.x + hv.x + bv[r].x,
                                    acc0.y + acc1.y + hv.y + bv[r].y,
                                    acc0.z + acc1.z + hv.z + bv[r].z,
                                    acc0.w + acc1.w + hv.w + bv[r].w);
            if (dorelu) {
                v4.x = fmaxf(v4.x, 0.f); v4.y = fmaxf(v4.y, 0.f);
                v4.z = fmaxf(v4.z, 0.f); v4.w = fmaxf(v4.w, 0.f);
            }
            tot.x += v4.x; tot.y += v4.y; tot.z += v4.z; tot.w += v4.w;
        }
        *(float4*)(t + (size_t)n * DD + lane * 4) = tot;
        bsum.x += tot.x; bsum.y += tot.y; bsum.z += tot.z; bsum.w += tot.w;
        bsq.x += tot.x * tot.x; bsq.y += tot.y * tot.y;
        bsq.z += tot.z * tot.z; bsq.w += tot.w * tot.w;
    }

    // block-level BN stat reduction
    __shared__ float sb[8][DD], sb2[8][DD];
    *(float4*)(&sb[wid][lane * 4])  = bsum;
    *(float4*)(&sb2[wid][lane * 4]) = bsq;
    __syncthreads();
    int tid = threadIdx.x;
    if (tid < DD) {
        float s = 0.f;
#pragma unroll
        for (int w = 0; w < 8; w++) s += sb[w][tid];
        atomicAdd(&g_sum[tid], s);
    } else {
        int col = tid - DD;
        float s2 = 0.f;
#pragma unroll
        for (int w = 0; w < 8; w++) s2 += sb2[w][col];
        atomicAdd(&g_sumsq[col], s2);
    }

    // last block finalizes BN affine (and resets for replay determinism)
    __shared__ int s_last;
    __threadfence();
    if (tid == 0) s_last = (atomicAdd(&g_bar, 1) == (int)gridDim.x - 1);
    __syncthreads();
    if (s_last) {
        if (tid < DD) {
            float invN = 1.f / (float)NN;
            float mu  = g_sum[tid] * invN;
            float var = g_sumsq[tid] * invN - mu * mu;
            float rs  = rsqrtf(var + 1e-5f);
            float g   = gamma[tid];
            g_scale[tid] = rs * g;
            g_shift[tid] = beta[tid] - mu * rs * g;
            g_sum[tid] = 0.f;
            g_sumsq[tid] = 0.f;
        }
        if (tid == 0) g_bar = 0;
    }
}

// ---------------- launcher ----------------
extern "C" void kernel_launch(void* const* d_in, const int* in_sizes, int n_in,
                              void* d_out, int out_size) {
    const float* x     = (const float*)d_in[0];
    const int*   src   = (const int*)d_in[1];
    const int*   dst   = (const int*)d_in[2];
    const float* Ws    = (const float*)d_in[3];
    const float* attnl = (const float*)d_in[4];
    const float* attnr = (const float*)d_in[5];
    const float* bias  = (const float*)d_in[6];
    const float* gamma = (const float*)d_in[7];
    const float* beta  = (const float*)d_in[8];
    float* out = (float*)d_out;

    float* p_b0 = nullptr;
    __half *p_wt = nullptr, *p_hn = nullptr;
    cudaGetSymbolAddress((void**)&p_b0, g_b0);
    cudaGetSymbolAddress((void**)&p_wt, g_wt);
    cudaGetSymbolAddress((void**)&p_hn, g_hn);

    const int SMEM_BYTES = 2 * 128 * PAD * (int)sizeof(__half);  // 69632
    cudaFuncSetAttribute(gemm_hmma_kernel,
                         cudaFuncAttributeMaxDynamicSharedMemorySize, SMEM_BYTES);

    dim3 gemm_grid((NN + 127) / 128, RR);
    dim3 edge_grid((EE + 255) / 256, RR);
    dim3 scan_grid(SCAN_B, RR);
    dim3 nodew_grid((NN + 7) / 8, RR);   // warp per node
    int heavy_blocks = 1184;
    int norm_blocks  = ((NN * DD / 4) + 255) / 256;

    // ---- setup ----
    wconv_kernel<<<LL * RR, 256>>>(Ws);                 // #1 (also zeroes g_cnt)
    xconv_kernel<<<norm_blocks, 256>>>(x, p_hn);        // #2
    count_kernel<<<edge_grid, 256>>>(dst);              // #3
    gemm_hmma_kernel<<<gemm_grid, 256, SMEM_BYTES>>>(   // #4: layer-0 GEMM
        p_hn, p_wt, attnl, attnr);
    scan1_kernel<<<scan_grid, 1024>>>();                // #5
    scan3_kernel<<<scan_grid, 1024>>>();                // #6 (scan2 folded in)
    fill_kernel<<<edge_grid, 256>>>(src, dst);          // #7

    for (int i = 0; i < LL; i++) {
        float* tbuf = (i < LL - 1) ? p_b0 : out;

        if (i > 0) {
            gemm_hmma_kernel<<<gemm_grid, 256, SMEM_BYTES>>>(
                p_hn,
                p_wt  + (size_t)i * RR * DD * DD,
                attnl + (size_t)i * RR * DD,
                attnr + (size_t)i * RR * DD);
        }
        edgew_kernel<<<nodew_grid, 256>>>();
        heavy_all_kernel<<<heavy_blocks, 256>>>(
            p_hn,
            bias + (size_t)i * RR * DD,
            tbuf, /*dorelu=*/(i < LL - 1),
            gamma + (size_t)i * DD,
            beta  + (size_t)i * DD);
        if (i < LL - 1)
            hnconv_kernel<<<norm_blocks, 256>>>(tbuf, p_hn);
        else
            bnnorm_kernel<<<norm_blocks, 256>>>(out, out);
    }
}